// round 7
// baseline (speedup 1.0000x reference)
#include <cuda_runtime.h>
#include <cstdint>

#define NROWS 4096
#define TWO_N 8192
#define DDIM  64
#define BM 128
#define NTILES 64              // 8192 / 128
#define NPAIRS 2080            // 64*65/2 upper-triangular tile pairs
#define INV_T 20.0f
#define PRESCALE 5.3715827f    // sqrt(20 * log2(e)); dot of scaled = ex2 exponent

// sim smem layout
#define OFF_A    0             // 128x64 bf16 swizzled (16KB)
#define OFF_B    16384         // 16KB
#define SMEM_BYTES 32768

__device__ float g_pt[TWO_N];
__device__ float g_ps[TWO_N];

static __device__ __forceinline__ uint32_t smem_u32(const void* p) {
    uint32_t a;
    asm("{ .reg .u64 t; cvta.to.shared.u64 t, %1; cvt.u32.u64 %0, t; }" : "=r"(a) : "l"(p));
    return a;
}
static __device__ __forceinline__ float ex2f(float x) {
    float r; asm("ex2.approx.f32 %0, %1;" : "=f"(r) : "f"(x)); return r;
}
static __device__ __forceinline__ uint32_t bf16pack(float lo, float hi) {
    uint32_t r; asm("cvt.rn.bf16x2.f32 %0, %1, %2;" : "=r"(r) : "f"(hi), "f"(lo)); return r;
}

#define LDSM4(r0, r1, r2, r3, addr) \
    asm volatile("ldmatrix.sync.aligned.m8n8.x4.shared.b16 {%0,%1,%2,%3}, [%4];" \
                 : "=r"(r0), "=r"(r1), "=r"(r2), "=r"(r3) : "r"(addr))

#define MMA16816(d, a, b0, b1) \
    asm volatile("mma.sync.aligned.m16n8k16.row.col.f32.bf16.bf16.f32 " \
                 "{%0,%1,%2,%3}, {%4,%5,%6,%7}, {%8,%9}, {%0,%1,%2,%3};" \
                 : "+f"((d)[0]), "+f"((d)[1]), "+f"((d)[2]), "+f"((d)[3]) \
                 : "r"((a)[0]), "r"((a)[1]), "r"((a)[2]), "r"((a)[3]), "r"(b0), "r"(b1))

// ---- sim: upper-triangular tile pairs; fused fp32->bf16 convert in prologue;
//      row sums always, col sums (shuffle-transposed) when ti<tj ----
__global__ void __launch_bounds__(256, 2)
sim_kernel(const float* __restrict__ f1, const float* __restrict__ f2,
           const int* __restrict__ label) {
    extern __shared__ __align__(1024) char smem[];
    const uint32_t sb = smem_u32(smem);
    const int tid  = threadIdx.x;
    const int lane = tid & 31;
    const int wid  = tid >> 5;
    const int warpM = wid >> 1;
    const int warpN = wid & 1;

    // map linear pair index -> (ti, tj), ti <= tj
    const int t = blockIdx.x;
    int ti = (int)(64.5f - sqrtf(64.5f * 64.5f - 2.0f * (float)t));
    while (64 * ti - ti * (ti - 1) / 2 > t) ti--;
    while (64 * (ti + 1) - (ti + 1) * ti / 2 <= t) ti++;
    const int tj = ti + (t - (64 * ti - ti * (ti - 1) / 2));
    const int row0 = ti * BM;
    const int col0 = tj * BM;

    // prologue: read fp32 rows, prescale, pack bf16, store swizzled
#pragma unroll
    for (int it = 0; it < 8; it++) {
        int s = it * 256 + tid;              // 0..2047
        int r = s >> 4, q = s & 15;
        uint32_t sw = (uint32_t)((q * 8) ^ ((r & 7) << 4));
        {
            int gr = row0 + r;
            const float4* src = (gr < NROWS) ? (const float4*)(f1 + gr * DDIM)
                                             : (const float4*)(f2 + (gr - NROWS) * DDIM);
            float4 v = src[q];
            *(uint2*)(smem + OFF_A + r * 128 + sw) =
                make_uint2(bf16pack(v.x * PRESCALE, v.y * PRESCALE),
                           bf16pack(v.z * PRESCALE, v.w * PRESCALE));
        }
        {
            int gc = col0 + r;
            const float4* src = (gc < NROWS) ? (const float4*)(f1 + gc * DDIM)
                                             : (const float4*)(f2 + (gc - NROWS) * DDIM);
            float4 v = src[q];
            *(uint2*)(smem + OFF_B + r * 128 + sw) =
                make_uint2(bf16pack(v.x * PRESCALE, v.y * PRESCALE),
                           bf16pack(v.z * PRESCALE, v.w * PRESCALE));
        }
    }

    int rowA[2], nB[4];
#pragma unroll
    for (int mb = 0; mb < 2; mb++)
        rowA[mb] = warpM * 32 + mb * 16 + (lane & 7) + ((lane >> 3) & 1) * 8;
#pragma unroll
    for (int pr = 0; pr < 4; pr++)
        nB[pr] = warpN * 64 + pr * 16 + (lane & 7) + ((lane >> 4) & 1) * 8;
    const int kaA = (lane >> 4) * 16;
    const int kbB = ((lane >> 3) & 1) * 16;

    // per-thread labels (global, cached)
    int labR[4];
#pragma unroll
    for (int mb = 0; mb < 2; mb++)
#pragma unroll
        for (int h = 0; h < 2; h++) {
            int grow = row0 + warpM * 32 + mb * 16 + (lane >> 2) + h * 8;
            labR[mb * 2 + h] = label[grow & (NROWS - 1)];
        }

    __syncthreads();

    float acc[2][8][4];
#pragma unroll
    for (int mb = 0; mb < 2; mb++)
#pragma unroll
        for (int nb = 0; nb < 8; nb++)
#pragma unroll
            for (int e = 0; e < 4; e++) acc[mb][nb][e] = 0.f;

#pragma unroll
    for (int kc = 0; kc < 4; kc++) {
        uint32_t a[2][4];
#pragma unroll
        for (int mb = 0; mb < 2; mb++) {
            uint32_t addr = sb + OFF_A + rowA[mb] * 128
                          + ((kc * 32 + kaA) ^ ((rowA[mb] & 7) << 4));
            LDSM4(a[mb][0], a[mb][1], a[mb][2], a[mb][3], addr);
        }
#pragma unroll
        for (int pr = 0; pr < 4; pr++) {
            uint32_t b0, b1, b2, b3;
            uint32_t addr = sb + OFF_B + nB[pr] * 128
                          + ((kc * 32 + kbB) ^ ((nB[pr] & 7) << 4));
            LDSM4(b0, b1, b2, b3, addr);
#pragma unroll
            for (int mb = 0; mb < 2; mb++) {
                MMA16816(acc[mb][2 * pr],     a[mb], b0, b1);
                MMA16816(acc[mb][2 * pr + 1], a[mb], b2, b3);
            }
        }
    }

    // epilogue: exp + row sums (always) + col sums via shuffle reduce (ti<tj)
    const bool offdiag = (ti != tj);
    float tot[4] = {0.f, 0.f, 0.f, 0.f};
    float smv[4] = {0.f, 0.f, 0.f, 0.f};

#pragma unroll
    for (int nb = 0; nb < 8; nb++) {
        int ci = col0 + warpN * 64 + nb * 8 + (lane & 3) * 2;
        int2 lb2 = *(const int2*)(label + (ci & (NROWS - 1)));
        float ct0 = 0.f, ct1 = 0.f, cs0 = 0.f, cs1 = 0.f;
#pragma unroll
        for (int mb = 0; mb < 2; mb++)
#pragma unroll
            for (int h = 0; h < 2; h++) {
                float e0 = ex2f(acc[mb][nb][2 * h]);
                float e1 = ex2f(acc[mb][nb][2 * h + 1]);
                float m0 = (lb2.x == labR[mb * 2 + h]) ? e0 : 0.f;
                float m1 = (lb2.y == labR[mb * 2 + h]) ? e1 : 0.f;
                tot[mb * 2 + h] += e0 + e1;
                smv[mb * 2 + h] += m0 + m1;
                ct0 += e0; ct1 += e1;
                cs0 += m0; cs1 += m1;
            }
        if (offdiag) {
#pragma unroll
            for (int o = 4; o <= 16; o <<= 1) {
                ct0 += __shfl_xor_sync(0xffffffffu, ct0, o);
                ct1 += __shfl_xor_sync(0xffffffffu, ct1, o);
                cs0 += __shfl_xor_sync(0xffffffffu, cs0, o);
                cs1 += __shfl_xor_sync(0xffffffffu, cs1, o);
            }
            if ((lane >> 2) == 0) {
                int gc = col0 + warpN * 64 + nb * 8 + (lane & 3) * 2;
                atomicAdd(&g_pt[gc],     ct0);
                atomicAdd(&g_pt[gc + 1], ct1);
                atomicAdd(&g_ps[gc],     cs0);
                atomicAdd(&g_ps[gc + 1], cs1);
            }
        }
    }

#pragma unroll
    for (int i = 0; i < 4; i++) {
        float tv = tot[i], sv = smv[i];
        tv += __shfl_xor_sync(0xffffffffu, tv, 1);
        tv += __shfl_xor_sync(0xffffffffu, tv, 2);
        sv += __shfl_xor_sync(0xffffffffu, sv, 1);
        sv += __shfl_xor_sync(0xffffffffu, sv, 2);
        if ((lane & 3) == 0) {
            int grow = row0 + warpM * 32 + (i >> 1) * 16 + (lane >> 2) + (i & 1) * 8;
            atomicAdd(&g_pt[grow], tv);
            atomicAdd(&g_ps[grow], sv);
        }
    }
}

// ---- finalize: hist (per-block) + pos dot + log term + global sum ----
__global__ void __launch_bounds__(128)
finalize_kernel(const float* __restrict__ f1, const float* __restrict__ f2,
                const int* __restrict__ label, float* __restrict__ out) {
    __shared__ int h[64];
    const int tid = threadIdx.x;
    if (tid < 64) h[tid] = 0;
    __syncthreads();
    for (int j = tid; j < NROWS; j += 128) atomicAdd(&h[label[j] & 63], 1);
    __syncthreads();

    int i = blockIdx.x * 128 + tid;          // 64 x 128 = 8192
    int i0 = i & (NROWS - 1);
    const float4* a = (const float4*)(f1 + i0 * DDIM);
    const float4* b = (const float4*)(f2 + i0 * DDIM);
    float d = 0.f;
#pragma unroll
    for (int u = 0; u < DDIM / 4; u++) {
        float4 x = a[u], y = b[u];
        d += x.x * y.x + x.y * y.y + x.z * y.z + x.w * y.w;
    }
    float pos  = __expf(d * INV_T);
    float Ng   = g_pt[i] - g_ps[i];
    float term = log1pf(Ng / pos);            // == -log(pos/(Ng+pos))
    int   gs   = 2 * h[label[i0] & 63];
    float val  = term / (float)gs;

#pragma unroll
    for (int o = 16; o > 0; o >>= 1) val += __shfl_down_sync(0xffffffffu, val, o);
    __shared__ float ws[4];
    int lane = tid & 31, w = tid >> 5;
    if (lane == 0) ws[w] = val;
    __syncthreads();
    if (w == 0) {
        val = (lane < 4) ? ws[lane] : 0.f;
#pragma unroll
        for (int o = 2; o > 0; o >>= 1) val += __shfl_down_sync(0xffffffffu, val, o);
        if (lane == 0) atomicAdd(out, val);
    }
}

extern "C" void kernel_launch(void* const* d_in, const int* in_sizes, int n_in,
                              void* d_out, int out_size) {
    (void)in_sizes; (void)n_in; (void)out_size;
    const float* f1    = (const float*)d_in[0];
    const float* f2    = (const float*)d_in[1];
    const int*   label = (const int*)d_in[2];
    float*       out   = (float*)d_out;

    cudaFuncSetAttribute(sim_kernel, cudaFuncAttributeMaxDynamicSharedMemorySize, SMEM_BYTES);

    void* pt_addr = nullptr;
    void* ps_addr = nullptr;
    cudaGetSymbolAddress(&pt_addr, g_pt);
    cudaGetSymbolAddress(&ps_addr, g_ps);
    cudaMemsetAsync(pt_addr, 0, TWO_N * sizeof(float));
    cudaMemsetAsync(ps_addr, 0, TWO_N * sizeof(float));
    cudaMemsetAsync(out, 0, sizeof(float));

    sim_kernel<<<NPAIRS, 256, SMEM_BYTES>>>(f1, f2, label);
    finalize_kernel<<<64, 128>>>(f1, f2, label, out);
}